// round 7
// baseline (speedup 1.0000x reference)
#include <cuda_runtime.h>
#include <cstdint>

#define EMBED 64
#define HID   128
#define MAXN  1000000
#define TILE_M 128

// Scratch: messages[N, 64]. __device__ global (no allocation allowed).
__device__ float g_msgs[(size_t)MAXN * EMBED];

// ---------------------------------------------------------------------------
// Packed fp32x2 helpers (Blackwell FFMA2 path — PTX only, ptxas won't fuse)
// ---------------------------------------------------------------------------
__device__ __forceinline__ unsigned long long pk2(float x, float y) {
    unsigned long long r;
    asm("mov.b64 %0, {%1, %2};" : "=l"(r) : "f"(x), "f"(y));
    return r;
}
__device__ __forceinline__ void upk2(unsigned long long v, float& x, float& y) {
    asm("mov.b64 {%0, %1}, %2;" : "=f"(x), "=f"(y) : "l"(v));
}
__device__ __forceinline__ unsigned long long ffma2(unsigned long long a,
                                                    unsigned long long b,
                                                    unsigned long long c) {
    unsigned long long d;
    asm("fma.rn.f32x2 %0, %1, %2, %3;" : "=l"(d) : "l"(a), "l"(b), "l"(c));
    return d;
}

// ---------------------------------------------------------------------------
// Kernel 0: no-op probe (keeps ncu -s 5 -c 1 landing on the MLP kernel)
// ---------------------------------------------------------------------------
__global__ void probe_kernel(int x) { (void)x; }

// ---------------------------------------------------------------------------
// Kernel 1: zero the message buffer
// ---------------------------------------------------------------------------
__global__ void zero_msgs_kernel(int n4) {
    int i = blockIdx.x * blockDim.x + threadIdx.x;
    if (i < n4) reinterpret_cast<float4*>(g_msgs)[i] = make_float4(0.f, 0.f, 0.f, 0.f);
}

// ---------------------------------------------------------------------------
// Kernel 2: scatter-add  messages[dst] += emb[src]   (edge_index int32)
// 16 threads/edge, red.global.add.v4.f32 (no return trip).
// ---------------------------------------------------------------------------
__global__ void scatter_kernel(const int* __restrict__ ei,
                               const float* __restrict__ emb, int E) {
    long long idx = (long long)blockIdx.x * blockDim.x + threadIdx.x;
    if (idx >= (long long)E * 16) return;
    int e  = (int)(idx >> 4);
    int d4 = (int)(idx & 15);
    int src = ei[e];
    int dst = ei[E + e];
    float4 v = reinterpret_cast<const float4*>(emb + (size_t)src * EMBED)[d4];
    float* o = g_msgs + (size_t)dst * EMBED + d4 * 4;
    asm volatile("red.global.add.v4.f32 [%0], {%1, %2, %3, %4};"
                 :: "l"(o), "f"(v.x), "f"(v.y), "f"(v.z), "f"(v.w)
                 : "memory");
}

// ---------------------------------------------------------------------------
// Kernel 3: fused 2-layer MLP + residual, persistent FFMA2 GEMM.
// 256 threads = 8 warps; warp w owns h-cols [16w,16w+16) / n-cols [8w,8w+8)
// so the weight operand is WARP-UNIFORM (pure LDS broadcast, 1 wavefront).
// Lane l owns node-pairs {l, l+32} (nodes 2l,2l+1, 2(l+32),2(l+32)+1).
//   GEMM1: acc[2 pairs][16 h], a = xs u64 col {l, l+32}, b = w1dup (16 u64)
//   GEMM2: acc[2 pairs][8 n],  a = hs u64 col {l, l+32}, b = w2dup (8 u64)
// xs[k][m] / hs[k][m] rows = 512 B: LDS.64/STS.64 2-phase conflict-free.
// ---------------------------------------------------------------------------
__global__ void __launch_bounds__(256) mlp_kernel(
    const float* __restrict__ emb,
    const float* __restrict__ w1, const float* __restrict__ b1,
    const float* __restrict__ w2, const float* __restrict__ b2,
    float* __restrict__ out, int N, int ntiles)
{
    extern __shared__ float smem[];
    float* xs  = smem;                 // [64][128]
    float* hs  = xs + 64 * 128;        // [128][128]
    float* w1d = hs + 128 * 128;       // [64][256]   {w,w} dup over h
    float* w2d = w1d + 64 * 256;       // [128][128]  {w,w} dup over n
    float* b1s = w2d + 128 * 128;      // [128]
    float* b2s = b1s + 128;            // [64]

    const int tid  = threadIdx.x;
    const int lane = tid & 31;
    const int wrp  = tid >> 5;

    // ---- stage duplicated weights + biases ONCE (persistent kernel) ----
    for (int i = tid; i < HID * EMBED; i += 256) {
        float v = w1[i];               // w1[h][d]
        int h = i >> 6, d = i & 63;
        w1d[d * 256 + 2 * h]     = v;
        w1d[d * 256 + 2 * h + 1] = v;
    }
    for (int i = tid; i < EMBED * HID; i += 256) {
        float v = w2[i];               // w2[n][h]
        int n = i >> 7, h = i & 127;
        w2d[h * 128 + 2 * n]     = v;
        w2d[h * 128 + 2 * n + 1] = v;
    }
    if (tid < HID)   b1s[tid] = b1[tid];
    if (tid < EMBED) b2s[tid] = b2[tid];

    const int h0 = wrp * 16;
    const int n0 = wrp * 8;
    unsigned long long* xsu = reinterpret_cast<unsigned long long*>(xs); // [64][64]
    unsigned long long* hsu = reinterpret_cast<unsigned long long*>(hs); // [128][64]

    for (int tile = blockIdx.x; tile < ntiles; tile += gridDim.x) {
        const int node0 = tile * TILE_M;

        // ---- stage msgs tile: xs[k][m] (lanes -> consecutive m, 0-conflict) ----
        #pragma unroll
        for (int j = 0; j < 8; j++) {
            int lin = tid + j * 256;
            int m  = lin & 127;
            int c4 = lin >> 7;         // 0..15
            int node = node0 + m;
            float4 v = make_float4(0.f, 0.f, 0.f, 0.f);
            if (node < N)
                v = reinterpret_cast<const float4*>(g_msgs + (size_t)node * EMBED)[c4];
            xs[(4 * c4 + 0) * 128 + m] = v.x;
            xs[(4 * c4 + 1) * 128 + m] = v.y;
            xs[(4 * c4 + 2) * 128 + m] = v.z;
            xs[(4 * c4 + 3) * 128 + m] = v.w;
        }
        __syncthreads();

        // ---------------- GEMM1: 2 pairs x 16 h per thread ----------------
        {
            unsigned long long acc0[16], acc1[16];
            #pragma unroll
            for (int j = 0; j < 16; j++) {
                float bb = b1s[h0 + j];
                unsigned long long bj = pk2(bb, bb);
                acc0[j] = bj; acc1[j] = bj;
            }
            #pragma unroll 4
            for (int k = 0; k < EMBED; k++) {
                unsigned long long a0 = xsu[k * 64 + lane];
                unsigned long long a1 = xsu[k * 64 + lane + 32];
                const ulonglong2* bp =
                    reinterpret_cast<const ulonglong2*>(&w1d[k * 256 + 2 * h0]);
                unsigned long long b[16];
                #pragma unroll
                for (int r = 0; r < 8; r++) {      // warp-uniform broadcasts
                    ulonglong2 t = bp[r];
                    b[2 * r] = t.x; b[2 * r + 1] = t.y;
                }
                #pragma unroll
                for (int j = 0; j < 16; j++) {
                    acc0[j] = ffma2(a0, b[j], acc0[j]);
                    acc1[j] = ffma2(a1, b[j], acc1[j]);
                }
            }
            // relu -> hs[h][m] (STS.64, 2-phase conflict-free)
            #pragma unroll
            for (int j = 0; j < 16; j++) {
                float x, y;
                upk2(acc0[j], x, y);
                hsu[(h0 + j) * 64 + lane] = pk2(fmaxf(x, 0.f), fmaxf(y, 0.f));
                upk2(acc1[j], x, y);
                hsu[(h0 + j) * 64 + lane + 32] = pk2(fmaxf(x, 0.f), fmaxf(y, 0.f));
            }
        }
        __syncthreads();

        // ---------------- GEMM2: 2 pairs x 8 n per thread ----------------
        {
            unsigned long long acc0[8], acc1[8];
            #pragma unroll
            for (int n = 0; n < 8; n++) {
                float bb = b2s[n0 + n];
                unsigned long long bn = pk2(bb, bb);
                acc0[n] = bn; acc1[n] = bn;
            }
            #pragma unroll 4
            for (int k = 0; k < HID; k++) {
                unsigned long long a0 = hsu[k * 64 + lane];
                unsigned long long a1 = hsu[k * 64 + lane + 32];
                const ulonglong2* bp =
                    reinterpret_cast<const ulonglong2*>(&w2d[k * 128 + 2 * n0]);
                unsigned long long b[8];
                #pragma unroll
                for (int r = 0; r < 4; r++) {      // warp-uniform broadcasts
                    ulonglong2 t = bp[r];
                    b[2 * r] = t.x; b[2 * r + 1] = t.y;
                }
                #pragma unroll
                for (int n = 0; n < 8; n++) {
                    acc0[n] = ffma2(a0, b[n], acc0[n]);
                    acc1[n] = ffma2(a1, b[n], acc1[n]);
                }
            }
            // epilogue: relu + residual, 2x float4 per node, 4 nodes/thread
            #pragma unroll
            for (int s = 0; s < 2; s++) {
                const unsigned long long* ac = s ? acc1 : acc0;
                int pairbase = lane + 32 * s;
                float lo[8], hi[8];
                #pragma unroll
                for (int n = 0; n < 8; n++) upk2(ac[n], lo[n], hi[n]);
                #pragma unroll
                for (int p = 0; p < 2; p++) {
                    int node = node0 + 2 * pairbase + p;
                    if (node < N) {
                        const float* vv = p ? hi : lo;
                        const float4* ep = reinterpret_cast<const float4*>(
                            emb + (size_t)node * EMBED + n0);
                        float4* op = reinterpret_cast<float4*>(
                            out + (size_t)node * EMBED + n0);
                        float4 e0 = ep[0], e1 = ep[1];
                        float4 o0, o1;
                        o0.x = e0.x + fmaxf(vv[0], 0.f);
                        o0.y = e0.y + fmaxf(vv[1], 0.f);
                        o0.z = e0.z + fmaxf(vv[2], 0.f);
                        o0.w = e0.w + fmaxf(vv[3], 0.f);
                        o1.x = e1.x + fmaxf(vv[4], 0.f);
                        o1.y = e1.y + fmaxf(vv[5], 0.f);
                        o1.z = e1.z + fmaxf(vv[6], 0.f);
                        o1.w = e1.w + fmaxf(vv[7], 0.f);
                        op[0] = o0; op[1] = o1;
                    }
                }
            }
        }
        __syncthreads();   // xs/hs safe to overwrite next tile
    }
}

// ---------------------------------------------------------------------------
// Launch
// ---------------------------------------------------------------------------
extern "C" void kernel_launch(void* const* d_in, const int* in_sizes, int n_in,
                              void* d_out, int out_size) {
    const int*   ei  = (const int*)d_in[0];   // edge_index [2, E] int32
    const float* emb = (const float*)d_in[1]; // [N, 64]
    const float* w1  = (const float*)d_in[2]; // [128, 64]
    const float* b1  = (const float*)d_in[3]; // [128]
    const float* w2  = (const float*)d_in[4]; // [64, 128]
    const float* b2  = (const float*)d_in[5]; // [64]
    float*       out = (float*)d_out;

    int E = in_sizes[0] / 2;
    int N = in_sizes[1] / EMBED;

    static int nsm = 0;
    if (nsm == 0) {
        cudaDeviceGetAttribute(&nsm, cudaDevAttrMultiProcessorCount, 0);
        if (nsm <= 0) nsm = 148;
    }

    // 0) capture-alignment probe (no-op)
    probe_kernel<<<1, 32>>>(0);

    // 1) zero messages
    int n4 = N * (EMBED / 4);
    zero_msgs_kernel<<<(n4 + 255) / 256, 256>>>(n4);

    // 2) scatter-add
    long long total = (long long)E * 16;
    scatter_kernel<<<(unsigned)((total + 255) / 256), 256>>>(ei, emb, E);

    // 3) fused persistent FFMA2 MLP + residual
    static const int SMEM_BYTES =
        (64 * 128 + 128 * 128 + 64 * 256 + 128 * 128 + HID + EMBED)
        * (int)sizeof(float);                      // 230,144 B
    cudaFuncSetAttribute(mlp_kernel, cudaFuncAttributeMaxDynamicSharedMemorySize,
                         SMEM_BYTES);
    int ntiles = (N + TILE_M - 1) / TILE_M;
    mlp_kernel<<<nsm, 256, SMEM_BYTES>>>(emb, w1, b1, w2, b2, out, N, ntiles);
}